// round 1
// baseline (speedup 1.0000x reference)
#include <cuda_runtime.h>

#define NB 8
#define NT 2048
#define NE 128
#define NH 16

// Q/K/V scratch (allocation-free: __device__ globals)
__device__ float g_Q[NB * NT * NH];
__device__ float g_K[NB * NT * NH];
__device__ float g_V[NB * NT * NH];

__device__ __forceinline__ float ex2f(float x) {
    float y;
    asm("ex2.approx.ftz.f32 %0, %1;" : "=f"(y) : "f"(x));
    return y;
}

// ---------------------------------------------------------------------------
// Kernel 1: fused QKV projection.
// CTA = 128 threads, 32 tokens. Thread (tg, og) computes 12 output columns
// (of 48 = Wq|Wk|Wv concatenated) for token tok0+tg.
// smem: x tile [32][132] (pad for conflict-free), W [128][48].
// ---------------------------------------------------------------------------
__global__ __launch_bounds__(128, 2) void qkv_kernel(
    const float* __restrict__ x,
    const float* __restrict__ Wq,
    const float* __restrict__ Wk,
    const float* __restrict__ Wv)
{
    __shared__ float4 sX[32 * 33];    // 32 tokens x 132 floats (33 float4/row)
    __shared__ float4 sW[128 * 12];   // 128 e-rows x 48 floats (12 float4/row)
    const int tid  = threadIdx.x;
    const int tok0 = blockIdx.x * 32;

    // load x tile (32 tokens x 128 floats = 1024 float4), coalesced
    const float4* xg = reinterpret_cast<const float4*>(x) + (size_t)tok0 * 32;
#pragma unroll
    for (int i = 0; i < 8; i++) {
        int idx = i * 128 + tid;
        sX[(idx >> 5) * 33 + (idx & 31)] = xg[idx];
    }
    // load W (128 x 48 floats = 1536 float4)
    const float4* wq4 = reinterpret_cast<const float4*>(Wq);
    const float4* wk4 = reinterpret_cast<const float4*>(Wk);
    const float4* wv4 = reinterpret_cast<const float4*>(Wv);
#pragma unroll
    for (int i = 0; i < 12; i++) {
        int idx = i * 128 + tid;       // 0..1535
        int e = idx / 12, c4 = idx % 12;
        float4 w = (c4 < 4) ? wq4[e * 4 + c4]
                 : (c4 < 8) ? wk4[e * 4 + (c4 - 4)]
                            : wv4[e * 4 + (c4 - 8)];
        sW[e * 12 + c4] = w;
    }
    __syncthreads();

    const int og = tid & 3;      // output group: 12 cols starting at og*12
    const int tg = tid >> 2;     // token within tile
    float acc[12];
#pragma unroll
    for (int i = 0; i < 12; i++) acc[i] = 0.f;

#pragma unroll 8
    for (int e4 = 0; e4 < 32; e4++) {
        float4 xv = sX[tg * 33 + e4];
        float xs[4] = {xv.x, xv.y, xv.z, xv.w};
#pragma unroll
        for (int u = 0; u < 4; u++) {
            const float4* wp = &sW[(e4 * 4 + u) * 12 + og * 3];
            float4 w0 = wp[0], w1 = wp[1], w2 = wp[2];
            acc[0]  = fmaf(xs[u], w0.x, acc[0]);
            acc[1]  = fmaf(xs[u], w0.y, acc[1]);
            acc[2]  = fmaf(xs[u], w0.z, acc[2]);
            acc[3]  = fmaf(xs[u], w0.w, acc[3]);
            acc[4]  = fmaf(xs[u], w1.x, acc[4]);
            acc[5]  = fmaf(xs[u], w1.y, acc[5]);
            acc[6]  = fmaf(xs[u], w1.z, acc[6]);
            acc[7]  = fmaf(xs[u], w1.w, acc[7]);
            acc[8]  = fmaf(xs[u], w2.x, acc[8]);
            acc[9]  = fmaf(xs[u], w2.y, acc[9]);
            acc[10] = fmaf(xs[u], w2.z, acc[10]);
            acc[11] = fmaf(xs[u], w2.w, acc[11]);
        }
    }
    const int tok = tok0 + tg;
#pragma unroll
    for (int k = 0; k < 3; k++) {
        int c0 = og * 12 + k * 4;   // 4-col blocks never straddle a matrix boundary
        float* base = (c0 < 16) ? g_Q : (c0 < 32) ? g_K : g_V;
        int h0 = c0 & 15;
        float4 o = make_float4(acc[k*4+0], acc[k*4+1], acc[k*4+2], acc[k*4+3]);
        *reinterpret_cast<float4*>(base + (size_t)tok * NH + h0) = o;
    }
}

// ---------------------------------------------------------------------------
// Kernel 2: causal flash attention (fp32, log2-domain online softmax).
// CTA = 128 threads, 64 queries; thread = (query, r), r in {0,1} splits keys
// even/odd inside each 128-key tile. Pair combined via shfl.xor(1).
// ---------------------------------------------------------------------------
__device__ __forceinline__ void kv_step(
    const float4* __restrict__ sK, const float4* __restrict__ sV, int j,
    const float4& q0, const float4& q1, const float4& q2, const float4& q3,
    float& m, float& l, float4& a0, float4& a1, float4& a2, float4& a3)
{
    float4 k0 = sK[j*4+0], k1 = sK[j*4+1], k2 = sK[j*4+2], k3 = sK[j*4+3];
    float s0 = fmaf(q0.w, k0.w, fmaf(q0.z, k0.z, fmaf(q0.y, k0.y, q0.x * k0.x)));
    float s1 = fmaf(q1.w, k1.w, fmaf(q1.z, k1.z, fmaf(q1.y, k1.y, q1.x * k1.x)));
    float s2 = fmaf(q2.w, k2.w, fmaf(q2.z, k2.z, fmaf(q2.y, k2.y, q2.x * k2.x)));
    float s3 = fmaf(q3.w, k3.w, fmaf(q3.z, k3.z, fmaf(q3.y, k3.y, q3.x * k3.x)));
    float s = (s0 + s1) + (s2 + s3);   // already in log2 units (q pre-scaled)
    float4 v0 = sV[j*4+0], v1 = sV[j*4+1], v2 = sV[j*4+2], v3 = sV[j*4+3];
    if (s > m) {                        // rare: new running max
        float c = ex2f(m - s);
        m = s;
        l = fmaf(l, c, 1.f);
        a0.x = fmaf(a0.x, c, v0.x); a0.y = fmaf(a0.y, c, v0.y);
        a0.z = fmaf(a0.z, c, v0.z); a0.w = fmaf(a0.w, c, v0.w);
        a1.x = fmaf(a1.x, c, v1.x); a1.y = fmaf(a1.y, c, v1.y);
        a1.z = fmaf(a1.z, c, v1.z); a1.w = fmaf(a1.w, c, v1.w);
        a2.x = fmaf(a2.x, c, v2.x); a2.y = fmaf(a2.y, c, v2.y);
        a2.z = fmaf(a2.z, c, v2.z); a2.w = fmaf(a2.w, c, v2.w);
        a3.x = fmaf(a3.x, c, v3.x); a3.y = fmaf(a3.y, c, v3.y);
        a3.z = fmaf(a3.z, c, v3.z); a3.w = fmaf(a3.w, c, v3.w);
    } else {                            // common path: 16 FFMA + 1 MUFU + 1 FADD
        float p = ex2f(s - m);
        l += p;
        a0.x = fmaf(p, v0.x, a0.x); a0.y = fmaf(p, v0.y, a0.y);
        a0.z = fmaf(p, v0.z, a0.z); a0.w = fmaf(p, v0.w, a0.w);
        a1.x = fmaf(p, v1.x, a1.x); a1.y = fmaf(p, v1.y, a1.y);
        a1.z = fmaf(p, v1.z, a1.z); a1.w = fmaf(p, v1.w, a1.w);
        a2.x = fmaf(p, v2.x, a2.x); a2.y = fmaf(p, v2.y, a2.y);
        a2.z = fmaf(p, v2.z, a2.z); a2.w = fmaf(p, v2.w, a2.w);
        a3.x = fmaf(p, v3.x, a3.x); a3.y = fmaf(p, v3.y, a3.y);
        a3.z = fmaf(p, v3.z, a3.z); a3.w = fmaf(p, v3.w, a3.w);
    }
}

__global__ __launch_bounds__(128, 2) void attn_kernel(float* __restrict__ out)
{
    __shared__ float4 sK[512];   // 128 keys x 16 floats
    __shared__ float4 sV[512];

    const int job = blockIdx.x;          // 256 jobs, heaviest first
    const int qt  = 31 - (job >> 3);     // q-tile (64 queries each)
    const int b   = job & 7;
    const int tid = threadIdx.x;
    const int ql  = tid >> 1;            // local query
    const int r   = tid & 1;             // key parity split
    const int qg  = qt * 64 + ql;        // global query row

    const float4* qp = reinterpret_cast<const float4*>(g_Q + ((size_t)b * NT + qg) * NH);
    const float SC = 0.25f * 1.44269504088896340736f;  // headsize^-.5 * log2(e)
    float4 q0 = qp[0], q1 = qp[1], q2 = qp[2], q3 = qp[3];
    q0.x *= SC; q0.y *= SC; q0.z *= SC; q0.w *= SC;
    q1.x *= SC; q1.y *= SC; q1.z *= SC; q1.w *= SC;
    q2.x *= SC; q2.y *= SC; q2.z *= SC; q2.w *= SC;
    q3.x *= SC; q3.y *= SC; q3.z *= SC; q3.w *= SC;

    float m = -1e30f, l = 0.f;
    float4 a0 = make_float4(0,0,0,0), a1 = a0, a2 = a0, a3 = a0;

    const int ntiles = (qt >> 1) + 1;
    const float4* Kg = reinterpret_cast<const float4*>(g_K + (size_t)b * NT * NH);
    const float4* Vg = reinterpret_cast<const float4*>(g_V + (size_t)b * NT * NH);

    for (int kt = 0; kt < ntiles; kt++) {
#pragma unroll
        for (int i = 0; i < 4; i++) {
            int idx = i * 128 + tid;
            sK[idx] = Kg[kt * 512 + idx];
            sV[idx] = Vg[kt * 512 + idx];
        }
        __syncthreads();

        int jlim = qg - (kt << 7);
        if (jlim >= 127) {
            // full tile: 64 keys per thread
#pragma unroll 8
            for (int jj = 0; jj < 64; jj++)
                kv_step(sK, sV, 2 * jj + r, q0, q1, q2, q3, m, l, a0, a1, a2, a3);
        } else {
            // diagonal tile: causal-bounded
            for (int j = r; j <= jlim; j += 2)
                kv_step(sK, sV, j, q0, q1, q2, q3, m, l, a0, a1, a2, a3);
        }
        __syncthreads();
    }

    // combine the (r=0, r=1) pair: lanes differ by 1
    const unsigned FULL = 0xffffffffu;
    float m2 = __shfl_xor_sync(FULL, m, 1);
    float l2 = __shfl_xor_sync(FULL, l, 1);
    float mx = fmaxf(m, m2);
    float cs = ex2f(m - mx);
    float co = ex2f(m2 - mx);
    float lt = fmaf(l, cs, l2 * co);
    float inv = 1.0f / lt;

    float oc[16];
    {
        float t;
        t = __shfl_xor_sync(FULL, a0.x, 1); oc[0]  = fmaf(a0.x, cs, t * co) * inv;
        t = __shfl_xor_sync(FULL, a0.y, 1); oc[1]  = fmaf(a0.y, cs, t * co) * inv;
        t = __shfl_xor_sync(FULL, a0.z, 1); oc[2]  = fmaf(a0.z, cs, t * co) * inv;
        t = __shfl_xor_sync(FULL, a0.w, 1); oc[3]  = fmaf(a0.w, cs, t * co) * inv;
        t = __shfl_xor_sync(FULL, a1.x, 1); oc[4]  = fmaf(a1.x, cs, t * co) * inv;
        t = __shfl_xor_sync(FULL, a1.y, 1); oc[5]  = fmaf(a1.y, cs, t * co) * inv;
        t = __shfl_xor_sync(FULL, a1.z, 1); oc[6]  = fmaf(a1.z, cs, t * co) * inv;
        t = __shfl_xor_sync(FULL, a1.w, 1); oc[7]  = fmaf(a1.w, cs, t * co) * inv;
        t = __shfl_xor_sync(FULL, a2.x, 1); oc[8]  = fmaf(a2.x, cs, t * co) * inv;
        t = __shfl_xor_sync(FULL, a2.y, 1); oc[9]  = fmaf(a2.y, cs, t * co) * inv;
        t = __shfl_xor_sync(FULL, a2.z, 1); oc[10] = fmaf(a2.z, cs, t * co) * inv;
        t = __shfl_xor_sync(FULL, a2.w, 1); oc[11] = fmaf(a2.w, cs, t * co) * inv;
        t = __shfl_xor_sync(FULL, a3.x, 1); oc[12] = fmaf(a3.x, cs, t * co) * inv;
        t = __shfl_xor_sync(FULL, a3.y, 1); oc[13] = fmaf(a3.y, cs, t * co) * inv;
        t = __shfl_xor_sync(FULL, a3.z, 1); oc[14] = fmaf(a3.z, cs, t * co) * inv;
        t = __shfl_xor_sync(FULL, a3.w, 1); oc[15] = fmaf(a3.w, cs, t * co) * inv;
    }

    if (r == 0) {
        float4* op = reinterpret_cast<float4*>(out + ((size_t)b * NT + qg) * NH);
        op[0] = make_float4(oc[0],  oc[1],  oc[2],  oc[3]);
        op[1] = make_float4(oc[4],  oc[5],  oc[6],  oc[7]);
        op[2] = make_float4(oc[8],  oc[9],  oc[10], oc[11]);
        op[3] = make_float4(oc[12], oc[13], oc[14], oc[15]);
    }
}

extern "C" void kernel_launch(void* const* d_in, const int* in_sizes, int n_in,
                              void* d_out, int out_size)
{
    const float* x  = (const float*)d_in[0];
    const float* Wq = (const float*)d_in[1];
    const float* Wk = (const float*)d_in[2];
    const float* Wv = (const float*)d_in[3];
    float* out = (float*)d_out;

    qkv_kernel<<<512, 128>>>(x, Wq, Wk, Wv);   // 16384 tokens / 32 per CTA
    attn_kernel<<<256, 128>>>(out);            // 8 batches x 32 q-tiles
}